// round 1
// baseline (speedup 1.0000x reference)
#include <cuda_runtime.h>
#include <math.h>
#include <stdint.h>

#define NN 50000
#define NE 800000
#define NGR 1024
#define CH 128
#define FIN 16
#define FE 3
#define NL 3
#define LOG2F_ 0.6931471805599453f
#define BN_EPS 1e-5f

// ---------------- scratch (device globals; no runtime alloc) ----------------
__device__ float g_h[NN * CH];
__device__ float g_hin[NN * CH];
__device__ float g_agg[NN * CH];
__device__ float g_env[NE];
__device__ float g_bnsum[CH];
__device__ float g_bnsq[CH];
__device__ float g_hg[NGR * CH];

__device__ __forceinline__ float sspf(float x) {
    // shifted softplus, numerically stable
    return fmaxf(x, 0.f) + log1pf(__expf(-fabsf(x))) - LOG2F_;
}

__device__ __forceinline__ void red_add_v4(float* addr, float a, float b, float c, float d) {
    asm volatile("red.global.add.v4.f32 [%0], {%1,%2,%3,%4};"
                 :: "l"(addr), "f"(a), "f"(b), "f"(c), "f"(d) : "memory");
}

// ---------------- embed stage 1: t1 = x @ W_l1 + b_l1 ----------------
__global__ void embed1_kernel(const float* __restrict__ x,
                              const float* __restrict__ W1,
                              const float* __restrict__ b1) {
    int idx = blockIdx.x * blockDim.x + threadIdx.x;
    if (idx >= NN * CH) return;
    int n = idx >> 7, j = idx & 127;
    const float* xr = x + n * FIN;
    float acc = b1[j];
#pragma unroll
    for (int f = 0; f < FIN; f++) acc += xr[f] * W1[f * CH + j];
    g_hin[idx] = acc;
}

// ---------------- generic node GEMM: [NN,128] @ [128,128] ----------------
// MODE 0: g_h   = g_hin @ W + b            (embed stage 2)
// MODE 1: g_hin = g_h   @ W + b            (interaction lin_in)
// MODE 2: g_h  += ssp(g_agg @ W + b)       (interaction lin_out + residual)
#define NODES_PER_BLOCK 32
#define NG_SMEM ((16384 + NODES_PER_BLOCK * CH) * 4)

template <int MODE>
__global__ __launch_bounds__(256) void node_gemm(const float* __restrict__ W,
                                                 const float* __restrict__ b) {
    extern __shared__ float sm[];
    float* WS = sm;               // 128x128
    float* XS = sm + 16384;       // 32x128
    const float* X = (MODE == 0) ? g_hin : (MODE == 1) ? g_h : g_agg;

    int tid = threadIdx.x;
    int nb = blockIdx.x * NODES_PER_BLOCK;
    for (int i = tid; i < 16384; i += 256) WS[i] = W[i];
    for (int i = tid; i < NODES_PER_BLOCK * CH; i += 256) {
        int n = nb + (i >> 7);
        XS[i] = (n < NN) ? X[n * CH + (i & 127)] : 0.f;
    }
    __syncthreads();

    int tx = tid & 15, ty = tid >> 4;
    int j0 = tx * 8;
    int n0 = ty * 2;

    float acc[16];
#pragma unroll
    for (int i = 0; i < 16; i++) acc[i] = 0.f;

#pragma unroll 4
    for (int k = 0; k < CH; k++) {
        float a0 = XS[n0 * CH + k];
        float a1 = XS[n0 * CH + CH + k];
        float4 w0 = *(const float4*)(WS + k * CH + j0);
        float4 w1 = *(const float4*)(WS + k * CH + j0 + 4);
        acc[0]  += a0 * w0.x; acc[1]  += a0 * w0.y; acc[2]  += a0 * w0.z; acc[3]  += a0 * w0.w;
        acc[4]  += a0 * w1.x; acc[5]  += a0 * w1.y; acc[6]  += a0 * w1.z; acc[7]  += a0 * w1.w;
        acc[8]  += a1 * w0.x; acc[9]  += a1 * w0.y; acc[10] += a1 * w0.z; acc[11] += a1 * w0.w;
        acc[12] += a1 * w1.x; acc[13] += a1 * w1.y; acc[14] += a1 * w1.z; acc[15] += a1 * w1.w;
    }

#pragma unroll
    for (int nn = 0; nn < 2; nn++) {
        int n = nb + n0 + nn;
        if (n >= NN) continue;
        float* base = ((MODE == 1) ? g_hin : g_h) + n * CH + j0;
#pragma unroll
        for (int j = 0; j < 8; j++) {
            float v = acc[nn * 8 + j] + b[j0 + j];
            if (MODE == 2) {
                base[j] += sspf(v);
            } else {
                base[j] = v;
            }
        }
    }
}

// ---------------- BatchNorm ----------------
__global__ void bn_stats_kernel() {
    int c = threadIdx.x;  // 128 threads
    float s = 0.f, q = 0.f;
    for (int n = blockIdx.x; n < NN; n += gridDim.x) {
        float v = g_h[n * CH + c];
        s += v; q += v * v;
    }
    atomicAdd(&g_bnsum[c], s);
    atomicAdd(&g_bnsq[c], q);
}

__global__ void bn_apply_kernel(const float* __restrict__ bn_g,
                                const float* __restrict__ bn_b) {
    int idx = blockIdx.x * blockDim.x + threadIdx.x;
    if (idx >= NN * CH) return;
    int c = idx & 127;
    float mu = g_bnsum[c] * (1.f / NN);
    float var = g_bnsq[c] * (1.f / NN) - mu * mu;
    g_h[idx] = (g_h[idx] - mu) * rsqrtf(var + BN_EPS) * bn_g[c] + bn_b[c];
}

// ---------------- cosine cutoff envelope ----------------
__global__ void env_kernel(const float* __restrict__ ew) {
    int idx = blockIdx.x * blockDim.x + threadIdx.x;
    if (idx >= NE) return;
    g_env[idx] = 0.5f * (cosf(ew[idx] * 0.31415926535897931f) + 1.f);
}

// ---------------- fused edge kernel ----------------
// per 128-edge tile: t = ssp(ea@We1+be1); filt = t@We2+be2;
// msg = hin[src]*filt*env; agg[dst] += msg (vector RED)
#define EDGE_SMEM ((16384 + 16384 + 384 + 128 + 128 + 128) * 4 + 256 * 4)

__global__ __launch_bounds__(256) void edge_kernel(
    const float* __restrict__ edge_attr,
    const int* __restrict__ src, const int* __restrict__ dst,
    const float* __restrict__ We1, const float* __restrict__ be1,
    const float* __restrict__ We2, const float* __restrict__ be2) {
    extern __shared__ float sm[];
    float* WS   = sm;             // We2 128x128
    float* tS   = sm + 16384;     // t transposed [k][e]
    float* eaS  = sm + 32768;     // 128x3
    float* envS = eaS + 384;      // 128
    float* be1S = envS + 128;     // 128
    float* be2S = be1S + 128;     // 128
    int* srcS = (int*)(be2S + 128);
    int* dstS = srcS + 128;

    int tid = threadIdx.x;
    int e0 = blockIdx.x * 128;

    for (int i = tid; i < 16384; i += 256) WS[i] = We2[i];
    for (int i = tid; i < 384; i += 256) eaS[i] = edge_attr[e0 * 3 + i];
    if (tid < 128) {
        envS[tid] = g_env[e0 + tid];
        be1S[tid] = be1[tid];
        be2S[tid] = be2[tid];
        srcS[tid] = src[e0 + tid];
        dstS[tid] = dst[e0 + tid];
    }
    __syncthreads();

    // phase 1: t[k][e] = ssp(ea[e] . We1[:,k] + be1[k])
    for (int idx = tid; idx < 16384; idx += 256) {
        int e = idx & 127, k = idx >> 7;
        float u = be1S[k]
                + eaS[e * 3 + 0] * __ldg(We1 + k)
                + eaS[e * 3 + 1] * __ldg(We1 + CH + k)
                + eaS[e * 3 + 2] * __ldg(We1 + 2 * CH + k);
        tS[k * CH + e] = sspf(u);
    }
    __syncthreads();

    // phase 2: register-blocked 128x128x128 GEMM, 8x8 per thread
    int tx = tid & 15, ty = tid >> 4;
    int j0 = tx * 8, el0 = ty * 8;
    float acc[64];
#pragma unroll
    for (int i = 0; i < 64; i++) acc[i] = 0.f;

#pragma unroll 2
    for (int k = 0; k < CH; k++) {
        float4 a0 = *(const float4*)(tS + k * CH + el0);
        float4 a1 = *(const float4*)(tS + k * CH + el0 + 4);
        float4 w0 = *(const float4*)(WS + k * CH + j0);
        float4 w1 = *(const float4*)(WS + k * CH + j0 + 4);
        float a[8] = {a0.x, a0.y, a0.z, a0.w, a1.x, a1.y, a1.z, a1.w};
        float w[8] = {w0.x, w0.y, w0.z, w0.w, w1.x, w1.y, w1.z, w1.w};
#pragma unroll
        for (int ei = 0; ei < 8; ei++)
#pragma unroll
            for (int ji = 0; ji < 8; ji++)
                acc[ei * 8 + ji] += a[ei] * w[ji];
    }

    // phase 3: epilogue — gather hin[src], modulate, scatter-add to agg[dst]
#pragma unroll
    for (int ei = 0; ei < 8; ei++) {
        int e = el0 + ei;
        int s = srcS[e];
        int d = dstS[e];
        float ev = envS[e];
        const float4 h0 = *(const float4*)(g_hin + (size_t)s * CH + j0);
        const float4 h1 = *(const float4*)(g_hin + (size_t)s * CH + j0 + 4);
        float m0 = h0.x * (acc[ei * 8 + 0] + be2S[j0 + 0]) * ev;
        float m1 = h0.y * (acc[ei * 8 + 1] + be2S[j0 + 1]) * ev;
        float m2 = h0.z * (acc[ei * 8 + 2] + be2S[j0 + 2]) * ev;
        float m3 = h0.w * (acc[ei * 8 + 3] + be2S[j0 + 3]) * ev;
        float m4 = h1.x * (acc[ei * 8 + 4] + be2S[j0 + 4]) * ev;
        float m5 = h1.y * (acc[ei * 8 + 5] + be2S[j0 + 5]) * ev;
        float m6 = h1.z * (acc[ei * 8 + 6] + be2S[j0 + 6]) * ev;
        float m7 = h1.w * (acc[ei * 8 + 7] + be2S[j0 + 7]) * ev;
        float* ap = g_agg + (size_t)d * CH + j0;
        red_add_v4(ap,     m0, m1, m2, m3);
        red_add_v4(ap + 4, m4, m5, m6, m7);
    }
}

// ---------------- graph pooling: hg[batch[n]] += h[n] ----------------
__global__ void pool_kernel(const int* __restrict__ batch) {
    int idx = blockIdx.x * blockDim.x + threadIdx.x;
    if (idx >= NN * 32) return;
    int n = idx >> 5, q = idx & 31;
    float4 v = *(const float4*)(g_h + (size_t)n * CH + q * 4);
    red_add_v4(g_hg + (size_t)batch[n] * CH + q * 4, v.x, v.y, v.z, v.w);
}

// ---------------- readout MLP ----------------
__global__ void readout_kernel(const float* __restrict__ W_r1,
                               const float* __restrict__ b_r1,
                               const float* __restrict__ W_r2,
                               const float* __restrict__ b_r2,
                               float* __restrict__ out) {
    int g = blockIdx.x;
    int t = threadIdx.x;  // 32 threads
    float acc = b_r1[t];
    for (int c = 0; c < CH; c++) acc += g_hg[g * CH + c] * W_r1[c * 32 + t];
    float r = sspf(acc);
    float p = r * W_r2[t];
#pragma unroll
    for (int o = 16; o; o >>= 1) p += __shfl_xor_sync(0xffffffffu, p, o);
    if (t == 0) out[g] = sspf(p + b_r2[0]);
}

// ---------------- launch ----------------
extern "C" void kernel_launch(void* const* d_in, const int* in_sizes, int n_in,
                              void* d_out, int out_size) {
    const float* x      = (const float*)d_in[0];
    const int*   eidx   = (const int*)d_in[1];
    const float* ew     = (const float*)d_in[2];
    const float* ea     = (const float*)d_in[3];
    const int*   batch  = (const int*)d_in[4];
    const float* W_l1   = (const float*)d_in[5];
    const float* b_l1   = (const float*)d_in[6];
    const float* W_l2   = (const float*)d_in[7];
    const float* b_l2   = (const float*)d_in[8];
    const float* bn_g   = (const float*)d_in[9];
    const float* bn_b   = (const float*)d_in[10];
    const float* Wi_in  = (const float*)d_in[11];
    const float* bi_in  = (const float*)d_in[12];
    const float* We1    = (const float*)d_in[13];
    const float* be1    = (const float*)d_in[14];
    const float* We2    = (const float*)d_in[15];
    const float* be2    = (const float*)d_in[16];
    const float* Wi_out = (const float*)d_in[17];
    const float* bi_out = (const float*)d_in[18];
    const float* W_r1   = (const float*)d_in[19];
    const float* b_r1   = (const float*)d_in[20];
    const float* W_r2   = (const float*)d_in[21];
    const float* b_r2   = (const float*)d_in[22];
    float* out = (float*)d_out;

    void *p_agg, *p_hg, *p_bns, *p_bnq;
    cudaGetSymbolAddress(&p_agg, g_agg);
    cudaGetSymbolAddress(&p_hg, g_hg);
    cudaGetSymbolAddress(&p_bns, g_bnsum);
    cudaGetSymbolAddress(&p_bnq, g_bnsq);

    cudaFuncSetAttribute(node_gemm<0>, cudaFuncAttributeMaxDynamicSharedMemorySize, NG_SMEM);
    cudaFuncSetAttribute(node_gemm<1>, cudaFuncAttributeMaxDynamicSharedMemorySize, NG_SMEM);
    cudaFuncSetAttribute(node_gemm<2>, cudaFuncAttributeMaxDynamicSharedMemorySize, NG_SMEM);
    cudaFuncSetAttribute(edge_kernel, cudaFuncAttributeMaxDynamicSharedMemorySize, EDGE_SMEM);

    cudaMemsetAsync(p_bns, 0, CH * sizeof(float));
    cudaMemsetAsync(p_bnq, 0, CH * sizeof(float));
    cudaMemsetAsync(p_hg, 0, NGR * CH * sizeof(float));

    const int ngemm_blocks = (NN + NODES_PER_BLOCK - 1) / NODES_PER_BLOCK;

    // node embedding
    embed1_kernel<<<(NN * CH + 255) / 256, 256>>>(x, W_l1, b_l1);
    node_gemm<0><<<ngemm_blocks, 256, NG_SMEM>>>(W_l2, b_l2);

    // batch norm
    bn_stats_kernel<<<256, 128>>>();
    bn_apply_kernel<<<(NN * CH + 255) / 256, 256>>>(bn_g, bn_b);

    // envelope
    env_kernel<<<(NE + 255) / 256, 256>>>(ew);

    // interaction layers
    for (int i = 0; i < NL; i++) {
        node_gemm<1><<<ngemm_blocks, 256, NG_SMEM>>>(Wi_in + i * CH * CH, bi_in + i * CH);
        cudaMemsetAsync(p_agg, 0, (size_t)NN * CH * sizeof(float));
        edge_kernel<<<NE / 128, 256, EDGE_SMEM>>>(ea, eidx, eidx + NE,
                                                  We1 + i * FE * CH, be1 + i * CH,
                                                  We2 + i * CH * CH, be2 + i * CH);
        node_gemm<2><<<ngemm_blocks, 256, NG_SMEM>>>(Wi_out + i * CH * CH, bi_out + i * CH);
    }

    // readout
    pool_kernel<<<(NN * 32 + 255) / 256, 256>>>(batch);
    readout_kernel<<<NGR, 32>>>(W_r1, b_r1, W_r2, b_r2, out);
}

// round 2
// speedup vs baseline: 1.6273x; 1.6273x over previous
#include <cuda_runtime.h>
#include <math.h>
#include <stdint.h>

#define NN 50000
#define NE 800000
#define NGR 1024
#define CH 128
#define FIN 16
#define FE 3
#define NL 3
#define LOG2F_ 0.6931471805599453f
#define BN_EPS 1e-5f
#define SA 132   // A-operand smem row stride (floats): banks 4r+t, conflict-free
#define SB 136   // B-operand smem row stride (floats): banks 8k+n, conflict-free

// ---------------- scratch (device globals; no runtime alloc) ----------------
__device__ float g_h[NN * CH];
__device__ float g_hin[NN * CH];
__device__ float g_agg[NN * CH];
__device__ float g_env[NE];
__device__ float g_bnsum[CH];
__device__ float g_bnsq[CH];
__device__ float g_hg[NGR * CH];

__device__ __forceinline__ float sspf(float x) {
    return fmaxf(x, 0.f) + log1pf(__expf(-fabsf(x))) - LOG2F_;
}

__device__ __forceinline__ void red_add_v4(float* addr, float a, float b, float c, float d) {
    asm volatile("red.global.add.v4.f32 [%0], {%1,%2,%3,%4};"
                 :: "l"(addr), "f"(a), "f"(b), "f"(c), "f"(d) : "memory");
}

__device__ __forceinline__ uint32_t f2tf(float f) {
    uint32_t r;
    asm("cvt.rna.tf32.f32 %0, %1;" : "=r"(r) : "f"(f));
    return r;
}

__device__ __forceinline__ void mma8(float c[4], uint32_t a0, uint32_t a1, uint32_t a2, uint32_t a3,
                                     uint32_t b0, uint32_t b1) {
    asm volatile("mma.sync.aligned.m16n8k8.row.col.f32.tf32.tf32.f32 "
                 "{%0,%1,%2,%3},{%4,%5,%6,%7},{%8,%9},{%0,%1,%2,%3};"
                 : "+f"(c[0]), "+f"(c[1]), "+f"(c[2]), "+f"(c[3])
                 : "r"(a0), "r"(a1), "r"(a2), "r"(a3), "r"(b0), "r"(b1));
}

// 128x128x128 tf32 tile GEMM. 8 warps: warp (wm,wn) owns 32 rows x 64 cols.
__device__ __forceinline__ void tile_mma_128(const uint32_t* __restrict__ tA,
                                             const uint32_t* __restrict__ tB,
                                             float acc[2][8][4],
                                             int wm, int wn, int gid, int tig) {
#pragma unroll 4
    for (int k0 = 0; k0 < CH; k0 += 8) {
        uint32_t a[2][4];
#pragma unroll
        for (int mi = 0; mi < 2; mi++) {
            int r = wm * 32 + mi * 16 + gid;
            a[mi][0] = tA[r * SA + k0 + tig];
            a[mi][1] = tA[(r + 8) * SA + k0 + tig];
            a[mi][2] = tA[r * SA + k0 + tig + 4];
            a[mi][3] = tA[(r + 8) * SA + k0 + tig + 4];
        }
#pragma unroll
        for (int ni = 0; ni < 8; ni++) {
            uint32_t b0 = tB[(k0 + tig) * SB + wn * 64 + ni * 8 + gid];
            uint32_t b1 = tB[(k0 + tig + 4) * SB + wn * 64 + ni * 8 + gid];
            mma8(acc[0][ni], a[0][0], a[0][1], a[0][2], a[0][3], b0, b1);
            mma8(acc[1][ni], a[1][0], a[1][1], a[1][2], a[1][3], b0, b1);
        }
    }
}

__device__ __forceinline__ void acc_store(float* S, float acc[2][8][4],
                                          int wm, int wn, int gid, int tig) {
#pragma unroll
    for (int mi = 0; mi < 2; mi++) {
        int r = wm * 32 + mi * 16 + gid;
#pragma unroll
        for (int ni = 0; ni < 8; ni++) {
            int c = wn * 64 + ni * 8 + 2 * tig;
            *(float2*)(S + r * SA + c) = make_float2(acc[mi][ni][0], acc[mi][ni][1]);
            *(float2*)(S + (r + 8) * SA + c) = make_float2(acc[mi][ni][2], acc[mi][ni][3]);
        }
    }
}

// ---------------- embed stage 1: t1 = x @ W_l1 + b_l1 ----------------
__global__ void embed1_kernel(const float* __restrict__ x,
                              const float* __restrict__ W1,
                              const float* __restrict__ b1) {
    int idx = blockIdx.x * blockDim.x + threadIdx.x;
    if (idx >= NN * CH) return;
    int n = idx >> 7, j = idx & 127;
    const float* xr = x + n * FIN;
    float acc = b1[j];
#pragma unroll
    for (int f = 0; f < FIN; f++) acc += xr[f] * W1[f * CH + j];
    g_hin[idx] = acc;
}

// ---------------- node GEMM (tf32 mma): [128-node tile,128] @ [128,128] ----------------
// MODE 0: g_h   = g_hin @ W + b
// MODE 1: g_hin = g_h   @ W + b
// MODE 2: g_h  += ssp(g_agg @ W + b)
#define NG_SMEM ((CH * SB + 128 * SA) * 4)

template <int MODE>
__global__ __launch_bounds__(256) void node_gemm(const float* __restrict__ W,
                                                 const float* __restrict__ b) {
    extern __shared__ float sm[];
    float* WSf = sm;
    float* XSf = sm + CH * SB;
    uint32_t* WS = (uint32_t*)WSf;
    uint32_t* XS = (uint32_t*)XSf;
    const float* X = (MODE == 0) ? g_hin : (MODE == 1) ? g_h : g_agg;

    int tid = threadIdx.x;
    int nb = blockIdx.x * 128;
    for (int i = tid; i < CH * CH; i += 256) {
        int k = i >> 7, n = i & 127;
        WS[k * SB + n] = f2tf(W[i]);
    }
    for (int i = tid; i < 128 * CH; i += 256) {
        int r = i >> 7, c = i & 127;
        int n = nb + r;
        XS[r * SA + c] = (n < NN) ? f2tf(X[(size_t)n * CH + c]) : 0u;
    }
    __syncthreads();

    int lane = tid & 31, w = tid >> 5;
    int gid = lane >> 2, tig = lane & 3;
    int wm = w & 3, wn = w >> 2;
    float acc[2][8][4];
#pragma unroll
    for (int i = 0; i < 2; i++)
#pragma unroll
        for (int j = 0; j < 8; j++)
#pragma unroll
            for (int q = 0; q < 4; q++) acc[i][j][q] = 0.f;

    tile_mma_128(XS, WS, acc, wm, wn, gid, tig);
    __syncthreads();
    acc_store(XSf, acc, wm, wn, gid, tig);
    __syncthreads();

    int tx = tid & 15, ty = tid >> 4;
    int j0 = tx * 8, r0 = ty * 8;
#pragma unroll
    for (int ri = 0; ri < 8; ri++) {
        int n = nb + r0 + ri;
        if (n >= NN) break;
        float4 v0 = *(float4*)(XSf + (r0 + ri) * SA + j0);
        float4 v1 = *(float4*)(XSf + (r0 + ri) * SA + j0 + 4);
        float o[8] = {v0.x, v0.y, v0.z, v0.w, v1.x, v1.y, v1.z, v1.w};
        float* base = ((MODE == 1) ? g_hin : g_h) + (size_t)n * CH + j0;
#pragma unroll
        for (int j = 0; j < 8; j++) {
            float v = o[j] + b[j0 + j];
            if (MODE == 2) base[j] += sspf(v);
            else base[j] = v;
        }
    }
}

// ---------------- BatchNorm ----------------
__global__ void bn_stats_kernel() {
    int c = threadIdx.x;  // 128 threads
    float s = 0.f, q = 0.f;
    for (int n = blockIdx.x; n < NN; n += gridDim.x) {
        float v = g_h[n * CH + c];
        s += v; q += v * v;
    }
    atomicAdd(&g_bnsum[c], s);
    atomicAdd(&g_bnsq[c], q);
}

__global__ void bn_apply_kernel(const float* __restrict__ bn_g,
                                const float* __restrict__ bn_b) {
    int idx = blockIdx.x * blockDim.x + threadIdx.x;
    if (idx >= NN * CH) return;
    int c = idx & 127;
    float mu = g_bnsum[c] * (1.f / NN);
    float var = g_bnsq[c] * (1.f / NN) - mu * mu;
    g_h[idx] = (g_h[idx] - mu) * rsqrtf(var + BN_EPS) * bn_g[c] + bn_b[c];
}

// ---------------- cosine cutoff envelope ----------------
__global__ void env_kernel(const float* __restrict__ ew) {
    int idx = blockIdx.x * blockDim.x + threadIdx.x;
    if (idx >= NE) return;
    g_env[idx] = 0.5f * (cosf(ew[idx] * 0.31415926535897931f) + 1.f);
}

// ---------------- fused edge kernel (tf32 mma filter GEMM) ----------------
#define EDGE_SMEM ((CH * SB + 128 * SA + 384 + 128 + 128 + 256) * 4)

__global__ __launch_bounds__(256) void edge_kernel(
    const float* __restrict__ edge_attr,
    const int* __restrict__ src, const int* __restrict__ dst,
    const float* __restrict__ We1, const float* __restrict__ be1,
    const float* __restrict__ We2, const float* __restrict__ be2) {
    extern __shared__ float sm[];
    float* WSf = sm;                    // We2 tf32 [k][n] stride SB
    float* tSf = sm + CH * SB;          // t tf32 [e][k] stride SA, later filt fp32
    uint32_t* WS = (uint32_t*)WSf;
    uint32_t* tS = (uint32_t*)tSf;
    float* eaS  = tSf + 128 * SA;       // 128x3
    float* envS = eaS + 384;
    float* be2S = envS + 128;
    int* srcS = (int*)(be2S + 128);
    int* dstS = srcS + 128;

    int tid = threadIdx.x;
    int e0 = blockIdx.x * 128;

    for (int i = tid; i < CH * CH; i += 256) {
        int k = i >> 7, n = i & 127;
        WS[k * SB + n] = f2tf(We2[i]);
    }
    for (int i = tid; i < 384; i += 256) eaS[i] = edge_attr[e0 * 3 + i];
    if (tid < 128) {
        envS[tid] = g_env[e0 + tid];
        be2S[tid] = be2[tid];
        srcS[tid] = src[e0 + tid];
        dstS[tid] = dst[e0 + tid];
    }
    __syncthreads();

    // phase 1: t[e][k] = ssp(ea[e] . We1[:,k] + be1[k]) as tf32
    for (int idx = tid; idx < 16384; idx += 256) {
        int e = idx >> 7, k = idx & 127;
        float u = __ldg(be1 + k)
                + eaS[e * 3 + 0] * __ldg(We1 + k)
                + eaS[e * 3 + 1] * __ldg(We1 + CH + k)
                + eaS[e * 3 + 2] * __ldg(We1 + 2 * CH + k);
        tS[e * SA + k] = f2tf(sspf(u));
    }
    __syncthreads();

    // phase 2: tensor-core 128x128x128 GEMM
    int lane = tid & 31, w = tid >> 5;
    int gid = lane >> 2, tig = lane & 3;
    int wm = w & 3, wn = w >> 2;
    float acc[2][8][4];
#pragma unroll
    for (int i = 0; i < 2; i++)
#pragma unroll
        for (int j = 0; j < 8; j++)
#pragma unroll
            for (int q = 0; q < 4; q++) acc[i][j][q] = 0.f;

    tile_mma_128(tS, WS, acc, wm, wn, gid, tig);
    __syncthreads();
    acc_store(tSf, acc, wm, wn, gid, tig);  // filt (no bias) now fp32 in tSf
    __syncthreads();

    // phase 3: epilogue — gather hin[src], modulate, scatter-add to agg[dst]
    int tx = tid & 15, ty = tid >> 4;
    int j0 = tx * 8, el0 = ty * 8;
#pragma unroll
    for (int ei = 0; ei < 8; ei++) {
        int e = el0 + ei;
        int s = srcS[e];
        int d = dstS[e];
        float ev = envS[e];
        float4 f0 = *(float4*)(tSf + e * SA + j0);
        float4 f1 = *(float4*)(tSf + e * SA + j0 + 4);
        const float4 h0 = *(const float4*)(g_hin + (size_t)s * CH + j0);
        const float4 h1 = *(const float4*)(g_hin + (size_t)s * CH + j0 + 4);
        float m0 = h0.x * (f0.x + be2S[j0 + 0]) * ev;
        float m1 = h0.y * (f0.y + be2S[j0 + 1]) * ev;
        float m2 = h0.z * (f0.z + be2S[j0 + 2]) * ev;
        float m3 = h0.w * (f0.w + be2S[j0 + 3]) * ev;
        float m4 = h1.x * (f1.x + be2S[j0 + 4]) * ev;
        float m5 = h1.y * (f1.y + be2S[j0 + 5]) * ev;
        float m6 = h1.z * (f1.z + be2S[j0 + 6]) * ev;
        float m7 = h1.w * (f1.w + be2S[j0 + 7]) * ev;
        float* ap = g_agg + (size_t)d * CH + j0;
        red_add_v4(ap,     m0, m1, m2, m3);
        red_add_v4(ap + 4, m4, m5, m6, m7);
    }
}

// ---------------- graph pooling ----------------
__global__ void pool_kernel(const int* __restrict__ batch) {
    int idx = blockIdx.x * blockDim.x + threadIdx.x;
    if (idx >= NN * 32) return;
    int n = idx >> 5, q = idx & 31;
    float4 v = *(const float4*)(g_h + (size_t)n * CH + q * 4);
    red_add_v4(g_hg + (size_t)batch[n] * CH + q * 4, v.x, v.y, v.z, v.w);
}

// ---------------- readout MLP ----------------
__global__ void readout_kernel(const float* __restrict__ W_r1,
                               const float* __restrict__ b_r1,
                               const float* __restrict__ W_r2,
                               const float* __restrict__ b_r2,
                               float* __restrict__ out) {
    int g = blockIdx.x;
    int t = threadIdx.x;  // 32 threads
    float acc = b_r1[t];
    for (int c = 0; c < CH; c++) acc += g_hg[g * CH + c] * W_r1[c * 32 + t];
    float r = sspf(acc);
    float p = r * W_r2[t];
#pragma unroll
    for (int o = 16; o; o >>= 1) p += __shfl_xor_sync(0xffffffffu, p, o);
    if (t == 0) out[g] = sspf(p + b_r2[0]);
}

// ---------------- launch ----------------
extern "C" void kernel_launch(void* const* d_in, const int* in_sizes, int n_in,
                              void* d_out, int out_size) {
    const float* x      = (const float*)d_in[0];
    const int*   eidx   = (const int*)d_in[1];
    const float* ew     = (const float*)d_in[2];
    const float* ea     = (const float*)d_in[3];
    const int*   batch  = (const int*)d_in[4];
    const float* W_l1   = (const float*)d_in[5];
    const float* b_l1   = (const float*)d_in[6];
    const float* W_l2   = (const float*)d_in[7];
    const float* b_l2   = (const float*)d_in[8];
    const float* bn_g   = (const float*)d_in[9];
    const float* bn_b   = (const float*)d_in[10];
    const float* Wi_in  = (const float*)d_in[11];
    const float* bi_in  = (const float*)d_in[12];
    const float* We1    = (const float*)d_in[13];
    const float* be1    = (const float*)d_in[14];
    const float* We2    = (const float*)d_in[15];
    const float* be2    = (const float*)d_in[16];
    const float* Wi_out = (const float*)d_in[17];
    const float* bi_out = (const float*)d_in[18];
    const float* W_r1   = (const float*)d_in[19];
    const float* b_r1   = (const float*)d_in[20];
    const float* W_r2   = (const float*)d_in[21];
    const float* b_r2   = (const float*)d_in[22];
    float* out = (float*)d_out;

    void *p_agg, *p_hg, *p_bns, *p_bnq;
    cudaGetSymbolAddress(&p_agg, g_agg);
    cudaGetSymbolAddress(&p_hg, g_hg);
    cudaGetSymbolAddress(&p_bns, g_bnsum);
    cudaGetSymbolAddress(&p_bnq, g_bnsq);

    cudaFuncSetAttribute(node_gemm<0>, cudaFuncAttributeMaxDynamicSharedMemorySize, NG_SMEM);
    cudaFuncSetAttribute(node_gemm<1>, cudaFuncAttributeMaxDynamicSharedMemorySize, NG_SMEM);
    cudaFuncSetAttribute(node_gemm<2>, cudaFuncAttributeMaxDynamicSharedMemorySize, NG_SMEM);
    cudaFuncSetAttribute(edge_kernel, cudaFuncAttributeMaxDynamicSharedMemorySize, EDGE_SMEM);

    cudaMemsetAsync(p_bns, 0, CH * sizeof(float));
    cudaMemsetAsync(p_bnq, 0, CH * sizeof(float));
    cudaMemsetAsync(p_hg, 0, NGR * CH * sizeof(float));

    const int ngemm_blocks = (NN + 127) / 128;

    embed1_kernel<<<(NN * CH + 255) / 256, 256>>>(x, W_l1, b_l1);
    node_gemm<0><<<ngemm_blocks, 256, NG_SMEM>>>(W_l2, b_l2);

    bn_stats_kernel<<<256, 128>>>();
    bn_apply_kernel<<<(NN * CH + 255) / 256, 256>>>(bn_g, bn_b);

    env_kernel<<<(NE + 255) / 256, 256>>>(ew);

    for (int i = 0; i < NL; i++) {
        node_gemm<1><<<ngemm_blocks, 256, NG_SMEM>>>(Wi_in + i * CH * CH, bi_in + i * CH);
        cudaMemsetAsync(p_agg, 0, (size_t)NN * CH * sizeof(float));
        edge_kernel<<<NE / 128, 256, EDGE_SMEM>>>(ea, eidx, eidx + NE,
                                                  We1 + i * FE * CH, be1 + i * CH,
                                                  We2 + i * CH * CH, be2 + i * CH);
        node_gemm<2><<<ngemm_blocks, 256, NG_SMEM>>>(Wi_out + i * CH * CH, bi_out + i * CH);
    }

    pool_kernel<<<(NN * 32 + 255) / 256, 256>>>(batch);
    readout_kernel<<<NGR, 32>>>(W_r1, b_r1, W_r2, b_r2, out);
}

// round 3
// speedup vs baseline: 2.7414x; 1.6846x over previous
#include <cuda_runtime.h>
#include <math.h>
#include <stdint.h>

#define NN 50000
#define NE 800000
#define NGR 1024
#define CH 128
#define FIN 16
#define FE 3
#define NL 3
#define ET 64            // edges per tile
#define NETILES (NE / ET)
#define LOG2F_ 0.6931471805599453f
#define BN_EPS 1e-5f
#define SA 132   // A-operand smem row stride (floats), conflict-free
#define SB 136   // B-operand smem row stride (floats), conflict-free

// ---------------- scratch (device globals; no runtime alloc) ----------------
__device__ float g_h[NN * CH];
__device__ float g_hin[NN * CH];
__device__ float g_agg[NN * CH];
__device__ float g_env[NE];
__device__ float g_bnsum[CH];
__device__ float g_bnsq[CH];
__device__ float g_hg[NGR * CH];

__device__ __forceinline__ float sspf(float x) {
    return fmaxf(x, 0.f) + log1pf(__expf(-fabsf(x))) - LOG2F_;
}

__device__ __forceinline__ void red_add_v4(float* addr, float a, float b, float c, float d) {
    asm volatile("red.global.add.v4.f32 [%0], {%1,%2,%3,%4};"
                 :: "l"(addr), "f"(a), "f"(b), "f"(c), "f"(d) : "memory");
}

__device__ __forceinline__ uint32_t f2tf(float f) {
    uint32_t r;
    asm("cvt.rna.tf32.f32 %0, %1;" : "=r"(r) : "f"(f));
    return r;
}

__device__ __forceinline__ void mma8(float c[4], uint32_t a0, uint32_t a1, uint32_t a2, uint32_t a3,
                                     uint32_t b0, uint32_t b1) {
    asm volatile("mma.sync.aligned.m16n8k8.row.col.f32.tf32.tf32.f32 "
                 "{%0,%1,%2,%3},{%4,%5,%6,%7},{%8,%9},{%0,%1,%2,%3};"
                 : "+f"(c[0]), "+f"(c[1]), "+f"(c[2]), "+f"(c[3])
                 : "r"(a0), "r"(a1), "r"(a2), "r"(a3), "r"(b0), "r"(b1));
}

// ---------------- embed stage 1 ----------------
__global__ void embed1_kernel(const float* __restrict__ x,
                              const float* __restrict__ W1,
                              const float* __restrict__ b1) {
    int idx = blockIdx.x * blockDim.x + threadIdx.x;
    if (idx >= NN * CH) return;
    int n = idx >> 7, j = idx & 127;
    const float* xr = x + n * FIN;
    float acc = b1[j];
#pragma unroll
    for (int f = 0; f < FIN; f++) acc += xr[f] * W1[f * CH + j];
    g_hin[idx] = acc;
}

// ---------------- persistent node GEMM: 64-node tiles, 2 blocks/SM ----------------
// MODE 0: g_h   = g_hin @ W + b
// MODE 1: g_hin = g_h   @ W + b
// MODE 2: g_h  += ssp(g_agg @ W + b)
#define NG_SMEM ((CH * SB + 64 * SA) * 4)

template <int MODE>
__global__ __launch_bounds__(256, 2) void node_gemm(const float* __restrict__ W,
                                                    const float* __restrict__ b) {
    extern __shared__ float sm[];
    uint32_t* WS = (uint32_t*)sm;          // [k][n], stride SB
    float* XSf = sm + CH * SB;             // 64 x SA
    uint32_t* XS = (uint32_t*)XSf;
    const float* X = (MODE == 0) ? g_hin : (MODE == 1) ? g_h : g_agg;

    int tid = threadIdx.x;
    for (int i = tid; i < CH * CH; i += 256)
        WS[(i >> 7) * SB + (i & 127)] = f2tf(W[i]);

    int lane = tid & 31, w = tid >> 5;
    int gid = lane >> 2, tig = lane & 3;
    int wm = w & 3, wn = w >> 2;
    int r0 = wm * 16 + gid;
    const int NT = (NN + 63) / 64;

    for (int tile = blockIdx.x; tile < NT; tile += gridDim.x) {
        int nb = tile * 64;
        __syncthreads();
        for (int i = tid; i < 64 * CH; i += 256) {
            int r = i >> 7, c = i & 127;
            int n = nb + r;
            XS[r * SA + c] = (n < NN) ? f2tf(X[(size_t)n * CH + c]) : 0u;
        }
        __syncthreads();

        float acc[8][4];
#pragma unroll
        for (int i = 0; i < 8; i++)
#pragma unroll
            for (int q = 0; q < 4; q++) acc[i][q] = 0.f;

#pragma unroll 4
        for (int k0 = 0; k0 < CH; k0 += 8) {
            int k1 = k0 + tig, k2 = k1 + 4;
            uint32_t a0 = XS[r0 * SA + k1];
            uint32_t a1 = XS[(r0 + 8) * SA + k1];
            uint32_t a2 = XS[r0 * SA + k2];
            uint32_t a3 = XS[(r0 + 8) * SA + k2];
#pragma unroll
            for (int ni = 0; ni < 8; ni++) {
                uint32_t b0 = WS[k1 * SB + wn * 64 + ni * 8 + gid];
                uint32_t b1 = WS[k2 * SB + wn * 64 + ni * 8 + gid];
                mma8(acc[ni], a0, a1, a2, a3, b0, b1);
            }
        }
        __syncthreads();
        // store accs back into XSf (fp32)
#pragma unroll
        for (int ni = 0; ni < 8; ni++) {
            int c = wn * 64 + ni * 8 + 2 * tig;
            *(float2*)(XSf + r0 * SA + c) = make_float2(acc[ni][0], acc[ni][1]);
            *(float2*)(XSf + (r0 + 8) * SA + c) = make_float2(acc[ni][2], acc[ni][3]);
        }
        __syncthreads();
        // epilogue
#pragma unroll
        for (int it = 0; it < 8; it++) {
            int chunk = tid + it * 256;          // 0..2047
            int r = chunk >> 5, cq = (chunk & 31) * 4;
            int n = nb + r;
            if (n >= NN) continue;
            float4 v = *(float4*)(XSf + r * SA + cq);
            float4 bb = *(const float4*)(b + cq);
            float* base = ((MODE == 1) ? g_hin : g_h) + (size_t)n * CH + cq;
            if (MODE == 2) {
                float4 old = *(float4*)base;
                old.x += sspf(v.x + bb.x);
                old.y += sspf(v.y + bb.y);
                old.z += sspf(v.z + bb.z);
                old.w += sspf(v.w + bb.w);
                *(float4*)base = old;
            } else {
                v.x += bb.x; v.y += bb.y; v.z += bb.z; v.w += bb.w;
                *(float4*)base = v;
            }
        }
    }
}

// ---------------- BatchNorm ----------------
__global__ void bn_stats_kernel() {
    int c = threadIdx.x;  // 128 threads
    float s = 0.f, q = 0.f;
    for (int n = blockIdx.x; n < NN; n += gridDim.x) {
        float v = g_h[n * CH + c];
        s += v; q += v * v;
    }
    atomicAdd(&g_bnsum[c], s);
    atomicAdd(&g_bnsq[c], q);
}

__global__ void bn_apply_kernel(const float* __restrict__ bn_g,
                                const float* __restrict__ bn_b) {
    int idx = blockIdx.x * blockDim.x + threadIdx.x;
    if (idx >= NN * CH) return;
    int c = idx & 127;
    float mu = g_bnsum[c] * (1.f / NN);
    float var = g_bnsq[c] * (1.f / NN) - mu * mu;
    g_h[idx] = (g_h[idx] - mu) * rsqrtf(var + BN_EPS) * bn_g[c] + bn_b[c];
}

// ---------------- cosine cutoff envelope ----------------
__global__ void env_kernel(const float* __restrict__ ew) {
    int idx = blockIdx.x * blockDim.x + threadIdx.x;
    if (idx >= NE) return;
    g_env[idx] = 0.5f * (cosf(ew[idx] * 0.31415926535897931f) + 1.f);
}

// ---------------- persistent fused edge kernel ----------------
// smem: We2 tf32 (CH*SB u32) + W1 packed (128 f4) + per-tile ea/env/be2/src/dst
#define EDGE_SMEM ((CH * SB + 512 + 256 + ET + CH) * 4 + 2 * ET * 4)

__global__ __launch_bounds__(256, 3) void edge_kernel(
    const float* __restrict__ edge_attr,
    const int* __restrict__ src, const int* __restrict__ dst,
    const float* __restrict__ We1, const float* __restrict__ be1,
    const float* __restrict__ We2, const float* __restrict__ be2) {
    extern __shared__ float sm[];
    uint32_t* WS = (uint32_t*)sm;                 // We2 tf32 [k][n] stride SB
    float4* W1p = (float4*)(sm + CH * SB);        // 128: (We1_0, We1_1, We1_2, be1)
    float4* eaS = (float4*)(sm + CH * SB + 512);  // 64
    float* envS = sm + CH * SB + 512 + 256;       // 64
    float* be2S = envS + ET;                      // 128
    int* srcS = (int*)(be2S + CH);                // 64
    int* dstS = srcS + ET;                        // 64

    int tid = threadIdx.x;
    for (int i = tid; i < CH * CH; i += 256)
        WS[(i >> 7) * SB + (i & 127)] = f2tf(We2[i]);
    if (tid < CH) {
        W1p[tid] = make_float4(We1[tid], We1[CH + tid], We1[2 * CH + tid], be1[tid]);
        be2S[tid] = be2[tid];
    }
    __syncthreads();

    int lane = tid & 31, w = tid >> 5;
    int gid = lane >> 2, tig = lane & 3;
    int wm = w & 3, wn = w >> 2;
    int r0 = wm * 16 + gid, r1 = r0 + 8;
    bool even = (tig & 1) == 0;
    int cb = wn * 64 + (tig >> 1) * 4;

    for (int tile = blockIdx.x; tile < NETILES; tile += gridDim.x) {
        int e0 = tile * ET;
        if (tid < ET) {
            const float* eap = edge_attr + (size_t)(e0 + tid) * 3;
            eaS[tid] = make_float4(eap[0], eap[1], eap[2], 0.f);
            envS[tid] = g_env[e0 + tid];
            srcS[tid] = src[e0 + tid];
            dstS[tid] = dst[e0 + tid];
        }
        __syncthreads();

        float4 eA = eaS[r0];
        float4 eB = eaS[r1];

        float acc[8][4];
#pragma unroll
        for (int i = 0; i < 8; i++)
#pragma unroll
            for (int q = 0; q < 4; q++) acc[i][q] = 0.f;

#pragma unroll 4
        for (int k0 = 0; k0 < CH; k0 += 8) {
            int k1 = k0 + tig, k2 = k1 + 4;
            float4 wa = W1p[k1];
            float4 wb = W1p[k2];
            float uA1 = fmaf(eA.x, wa.x, fmaf(eA.y, wa.y, fmaf(eA.z, wa.z, wa.w)));
            float uB1 = fmaf(eB.x, wa.x, fmaf(eB.y, wa.y, fmaf(eB.z, wa.z, wa.w)));
            float uA2 = fmaf(eA.x, wb.x, fmaf(eA.y, wb.y, fmaf(eA.z, wb.z, wb.w)));
            float uB2 = fmaf(eB.x, wb.x, fmaf(eB.y, wb.y, fmaf(eB.z, wb.z, wb.w)));
            uint32_t a0 = f2tf(sspf(uA1));
            uint32_t a1 = f2tf(sspf(uB1));
            uint32_t a2 = f2tf(sspf(uA2));
            uint32_t a3 = f2tf(sspf(uB2));
#pragma unroll
            for (int ni = 0; ni < 8; ni++) {
                uint32_t b0 = WS[k1 * SB + wn * 64 + ni * 8 + gid];
                uint32_t b1 = WS[k2 * SB + wn * 64 + ni * 8 + gid];
                mma8(acc[ni], a0, a1, a2, a3, b0, b1);
            }
        }

        // epilogue: pair lanes -> v4, gather hin, modulate, RED scatter
        int rr = even ? r0 : r1;
        int s = srcS[rr], d = dstS[rr];
        float ev = envS[rr];
        const float* hrow = g_hin + (size_t)s * CH;
        float* arow = g_agg + (size_t)d * CH;
#pragma unroll
        for (int ni = 0; ni < 8; ni++) {
            float sA = even ? acc[ni][2] : acc[ni][0];
            float rA = __shfl_xor_sync(0xffffffffu, sA, 1);
            float sB = even ? acc[ni][3] : acc[ni][1];
            float rB = __shfl_xor_sync(0xffffffffu, sB, 1);
            float fx, fy, fz, fw;
            if (even) { fx = acc[ni][0]; fy = acc[ni][1]; fz = rA; fw = rB; }
            else      { fx = rA; fy = rB; fz = acc[ni][2]; fw = acc[ni][3]; }
            int c = cb + ni * 8;
            float4 h = *(const float4*)(hrow + c);
            float4 bb = *(const float4*)(be2S + c);
            red_add_v4(arow + c,
                       h.x * (fx + bb.x) * ev,
                       h.y * (fy + bb.y) * ev,
                       h.z * (fz + bb.z) * ev,
                       h.w * (fw + bb.w) * ev);
        }
        __syncthreads();
    }
}

// ---------------- graph pooling ----------------
__global__ void pool_kernel(const int* __restrict__ batch) {
    int idx = blockIdx.x * blockDim.x + threadIdx.x;
    if (idx >= NN * 32) return;
    int n = idx >> 5, q = idx & 31;
    float4 v = *(const float4*)(g_h + (size_t)n * CH + q * 4);
    red_add_v4(g_hg + (size_t)batch[n] * CH + q * 4, v.x, v.y, v.z, v.w);
}

// ---------------- readout MLP ----------------
__global__ void readout_kernel(const float* __restrict__ W_r1,
                               const float* __restrict__ b_r1,
                               const float* __restrict__ W_r2,
                               const float* __restrict__ b_r2,
                               float* __restrict__ out) {
    int g = blockIdx.x;
    int t = threadIdx.x;  // 32 threads
    float acc = b_r1[t];
    for (int c = 0; c < CH; c++) acc += g_hg[g * CH + c] * W_r1[c * 32 + t];
    float r = sspf(acc);
    float p = r * W_r2[t];
#pragma unroll
    for (int o = 16; o; o >>= 1) p += __shfl_xor_sync(0xffffffffu, p, o);
    if (t == 0) out[g] = sspf(p + b_r2[0]);
}

// ---------------- launch ----------------
extern "C" void kernel_launch(void* const* d_in, const int* in_sizes, int n_in,
                              void* d_out, int out_size) {
    const float* x      = (const float*)d_in[0];
    const int*   eidx   = (const int*)d_in[1];
    const float* ew     = (const float*)d_in[2];
    const float* ea     = (const float*)d_in[3];
    const int*   batch  = (const int*)d_in[4];
    const float* W_l1   = (const float*)d_in[5];
    const float* b_l1   = (const float*)d_in[6];
    const float* W_l2   = (const float*)d_in[7];
    const float* b_l2   = (const float*)d_in[8];
    const float* bn_g   = (const float*)d_in[9];
    const float* bn_b   = (const float*)d_in[10];
    const float* Wi_in  = (const float*)d_in[11];
    const float* bi_in  = (const float*)d_in[12];
    const float* We1    = (const float*)d_in[13];
    const float* be1    = (const float*)d_in[14];
    const float* We2    = (const float*)d_in[15];
    const float* be2    = (const float*)d_in[16];
    const float* Wi_out = (const float*)d_in[17];
    const float* bi_out = (const float*)d_in[18];
    const float* W_r1   = (const float*)d_in[19];
    const float* b_r1   = (const float*)d_in[20];
    const float* W_r2   = (const float*)d_in[21];
    const float* b_r2   = (const float*)d_in[22];
    float* out = (float*)d_out;

    void *p_agg, *p_hg, *p_bns, *p_bnq;
    cudaGetSymbolAddress(&p_agg, g_agg);
    cudaGetSymbolAddress(&p_hg, g_hg);
    cudaGetSymbolAddress(&p_bns, g_bnsum);
    cudaGetSymbolAddress(&p_bnq, g_bnsq);

    cudaFuncSetAttribute(node_gemm<0>, cudaFuncAttributeMaxDynamicSharedMemorySize, NG_SMEM);
    cudaFuncSetAttribute(node_gemm<1>, cudaFuncAttributeMaxDynamicSharedMemorySize, NG_SMEM);
    cudaFuncSetAttribute(node_gemm<2>, cudaFuncAttributeMaxDynamicSharedMemorySize, NG_SMEM);
    cudaFuncSetAttribute(edge_kernel, cudaFuncAttributeMaxDynamicSharedMemorySize, EDGE_SMEM);

    cudaMemsetAsync(p_bns, 0, CH * sizeof(float));
    cudaMemsetAsync(p_bnq, 0, CH * sizeof(float));
    cudaMemsetAsync(p_hg, 0, NGR * CH * sizeof(float));

    const int ng_grid = 2 * 148;
    const int e_grid = 3 * 148;

    embed1_kernel<<<(NN * CH + 255) / 256, 256>>>(x, W_l1, b_l1);
    node_gemm<0><<<ng_grid, 256, NG_SMEM>>>(W_l2, b_l2);

    bn_stats_kernel<<<256, 128>>>();
    bn_apply_kernel<<<(NN * CH + 255) / 256, 256>>>(bn_g, bn_b);

    env_kernel<<<(NE + 255) / 256, 256>>>(ew);

    for (int i = 0; i < NL; i++) {
        node_gemm<1><<<ng_grid, 256, NG_SMEM>>>(Wi_in + i * CH * CH, bi_in + i * CH);
        cudaMemsetAsync(p_agg, 0, (size_t)NN * CH * sizeof(float));
        edge_kernel<<<e_grid, 256, EDGE_SMEM>>>(ea, eidx, eidx + NE,
                                                We1 + i * FE * CH, be1 + i * CH,
                                                We2 + i * CH * CH, be2 + i * CH);
        node_gemm<2><<<ng_grid, 256, NG_SMEM>>>(Wi_out + i * CH * CH, bi_out + i * CH);
    }

    pool_kernel<<<(NN * 32 + 255) / 256, 256>>>(batch);
    readout_kernel<<<NGR, 32>>>(W_r1, b_r1, W_r2, b_r2, out);
}

// round 5
// speedup vs baseline: 3.9576x; 1.4436x over previous
#include <cuda_runtime.h>
#include <math.h>
#include <stdint.h>

#define NN 50000
#define NE 800000
#define NGR 1024
#define CH 128
#define FIN 16
#define FE 3
#define NL 3
#define ET 64            // edges per tile
#define NETILES (NE / ET)
#define LN2F 0.69314718055994531f
#define L2EF 1.44269504088896341f
#define BN_EPS 1e-5f
#define SA 132   // A-operand smem row stride (floats), conflict-free
#define SB 136   // B-operand smem row stride (floats), conflict-free
#define SBU2 132 // edge B smem row stride in uint2 (264 floats, %32==8): conflict-free

// ---------------- scratch ----------------
__device__ float g_h[NN * CH];
__device__ float g_hin[NN * CH];
__device__ float g_agg[NN * CH];
__device__ float g_env[NE];
__device__ float g_bnsum[CH];
__device__ float g_bnsq[CH];
__device__ float g_hg[NGR * CH];

__device__ __forceinline__ float ex2f(float x) {
    float r;
    asm("ex2.approx.f32 %0, %1;" : "=f"(r) : "f"(x));
    return r;
}
__device__ __forceinline__ float lg2f(float x) {
    float r;
    asm("lg2.approx.f32 %0, %1;" : "=f"(r) : "f"(x));
    return r;
}

__device__ __forceinline__ float sspf(float x) {
    // shifted softplus via MUFU ex2/lg2 (2 MUFU + few FMA)
    float t = ex2f(-L2EF * fabsf(x));
    return fmaxf(x, 0.f) + LN2F * (lg2f(1.f + t) - 1.f);
}

__device__ __forceinline__ void red_add_v4(float* addr, float a, float b, float c, float d) {
    asm volatile("red.global.add.v4.f32 [%0], {%1,%2,%3,%4};"
                 :: "l"(addr), "f"(a), "f"(b), "f"(c), "f"(d) : "memory");
}

__device__ __forceinline__ uint32_t f2tf(float f) {
    uint32_t r;
    asm("cvt.rna.tf32.f32 %0, %1;" : "=r"(r) : "f"(f));
    return r;
}

__device__ __forceinline__ void mma8(float c[4], uint32_t a0, uint32_t a1, uint32_t a2, uint32_t a3,
                                     uint32_t b0, uint32_t b1) {
    asm volatile("mma.sync.aligned.m16n8k8.row.col.f32.tf32.tf32.f32 "
                 "{%0,%1,%2,%3},{%4,%5,%6,%7},{%8,%9},{%0,%1,%2,%3};"
                 : "+f"(c[0]), "+f"(c[1]), "+f"(c[2]), "+f"(c[3])
                 : "r"(a0), "r"(a1), "r"(a2), "r"(a3), "r"(b0), "r"(b1));
}

// ---------------- embed stage 1 ----------------
__global__ void embed1_kernel(const float* __restrict__ x,
                              const float* __restrict__ W1,
                              const float* __restrict__ b1) {
    int idx = blockIdx.x * blockDim.x + threadIdx.x;
    if (idx >= NN * CH) return;
    int n = idx >> 7, j = idx & 127;
    const float* xr = x + n * FIN;
    float acc = b1[j];
#pragma unroll
    for (int f = 0; f < FIN; f++) acc += xr[f] * W1[f * CH + j];
    g_hin[idx] = acc;
}

// ---------------- persistent node GEMM ----------------
// MODE 0: g_h   = g_hin @ W + b
// MODE 1: g_hin = g_h   @ W + b
// MODE 2: g_h  += ssp(g_agg @ W + b)   (+POOL: red to g_hg[batch])
#define NG_SMEM ((CH * SB + 64 * SA) * 4)

template <int MODE, int POOL>
__global__ __launch_bounds__(256, 2) void node_gemm(const float* __restrict__ W,
                                                    const float* __restrict__ b,
                                                    const int* __restrict__ batch) {
    extern __shared__ float sm[];
    uint32_t* WS = (uint32_t*)sm;          // [k][n], stride SB
    float* XSf = sm + CH * SB;             // 64 x SA
    uint32_t* XS = (uint32_t*)XSf;
    const float* X = (MODE == 0) ? g_hin : (MODE == 1) ? g_h : g_agg;

    int tid = threadIdx.x;
    for (int i = tid; i < CH * CH; i += 256)
        WS[(i >> 7) * SB + (i & 127)] = f2tf(W[i]);

    int lane = tid & 31, w = tid >> 5;
    int gid = lane >> 2, tig = lane & 3;
    int wm = w & 3, wn = w >> 2;
    int r0 = wm * 16 + gid;
    const int NT = (NN + 63) / 64;

    for (int tile = blockIdx.x; tile < NT; tile += gridDim.x) {
        int nb = tile * 64;
        __syncthreads();
        for (int i = tid; i < 64 * CH; i += 256) {
            int r = i >> 7, c = i & 127;
            int n = nb + r;
            XS[r * SA + c] = (n < NN) ? f2tf(X[(size_t)n * CH + c]) : 0u;
        }
        __syncthreads();

        float acc[8][4];
#pragma unroll
        for (int i = 0; i < 8; i++)
#pragma unroll
            for (int q = 0; q < 4; q++) acc[i][q] = 0.f;

#pragma unroll 4
        for (int k0 = 0; k0 < CH; k0 += 8) {
            int k1 = k0 + tig, k2 = k1 + 4;
            uint32_t a0 = XS[r0 * SA + k1];
            uint32_t a1 = XS[(r0 + 8) * SA + k1];
            uint32_t a2 = XS[r0 * SA + k2];
            uint32_t a3 = XS[(r0 + 8) * SA + k2];
#pragma unroll
            for (int ni = 0; ni < 8; ni++) {
                uint32_t b0 = WS[k1 * SB + wn * 64 + ni * 8 + gid];
                uint32_t b1 = WS[k2 * SB + wn * 64 + ni * 8 + gid];
                mma8(acc[ni], a0, a1, a2, a3, b0, b1);
            }
        }
        __syncthreads();
#pragma unroll
        for (int ni = 0; ni < 8; ni++) {
            int c = wn * 64 + ni * 8 + 2 * tig;
            *(float2*)(XSf + r0 * SA + c) = make_float2(acc[ni][0], acc[ni][1]);
            *(float2*)(XSf + (r0 + 8) * SA + c) = make_float2(acc[ni][2], acc[ni][3]);
        }
        __syncthreads();
#pragma unroll
        for (int it = 0; it < 8; it++) {
            int chunk = tid + it * 256;
            int r = chunk >> 5, cq = (chunk & 31) * 4;
            int n = nb + r;
            if (n >= NN) continue;
            float4 v = *(float4*)(XSf + r * SA + cq);
            float4 bb = *(const float4*)(b + cq);
            float* base = ((MODE == 1) ? g_hin : g_h) + (size_t)n * CH + cq;
            if (MODE == 2) {
                float4 old = *(float4*)base;
                old.x += sspf(v.x + bb.x);
                old.y += sspf(v.y + bb.y);
                old.z += sspf(v.z + bb.z);
                old.w += sspf(v.w + bb.w);
                *(float4*)base = old;
                if (POOL) {
                    int g = batch[n];
                    red_add_v4(g_hg + (size_t)g * CH + cq, old.x, old.y, old.z, old.w);
                }
            } else {
                v.x += bb.x; v.y += bb.y; v.z += bb.z; v.w += bb.w;
                *(float4*)base = v;
            }
        }
    }
}

// ---------------- BatchNorm ----------------
__global__ void bn_stats_kernel() {
    int c = threadIdx.x;
    float s = 0.f, q = 0.f;
    for (int n = blockIdx.x; n < NN; n += gridDim.x) {
        float v = g_h[n * CH + c];
        s += v; q += v * v;
    }
    atomicAdd(&g_bnsum[c], s);
    atomicAdd(&g_bnsq[c], q);
}

__global__ void bn_apply_kernel(const float* __restrict__ bn_g,
                                const float* __restrict__ bn_b) {
    int idx = blockIdx.x * blockDim.x + threadIdx.x;
    if (idx >= NN * CH) return;
    int c = idx & 127;
    float mu = g_bnsum[c] * (1.f / NN);
    float var = g_bnsq[c] * (1.f / NN) - mu * mu;
    g_h[idx] = (g_h[idx] - mu) * rsqrtf(var + BN_EPS) * bn_g[c] + bn_b[c];
}

// ---------------- envelope ----------------
__global__ void env_kernel(const float* __restrict__ ew) {
    int idx = blockIdx.x * blockDim.x + threadIdx.x;
    if (idx >= NE) return;
    g_env[idx] = 0.5f * (cosf(ew[idx] * 0.31415926535897931f) + 1.f);
}

// ---------------- persistent fused edge kernel ----------------
// 128 threads, 4 warps; warp w owns rows w*16..w*16+15(+8), all 128 cols.
// smem floats: WS2 (8448 u2 = 16896 f) | W1p 512 | eaS 256 | envS 64 | be2S 128 | src 64 | dst 64
#define EDGE_SMEM ((16896 + 512 + 256 + 64 + 128 + 64 + 64) * 4)

__global__ __launch_bounds__(128, 3) void edge_kernel(
    const float* __restrict__ edge_attr,
    const int* __restrict__ src, const int* __restrict__ dst,
    const float* __restrict__ We1, const float* __restrict__ be1,
    const float* __restrict__ We2, const float* __restrict__ be2) {
    extern __shared__ float sm[];
    uint2* WS2 = (uint2*)sm;                       // [(kg*4+tig)*SBU2 + n] = (tf32 W[k1][n], tf32 W[k1+4][n])
    float4* W1p = (float4*)(sm + 16896);           // 128: (We1_0, We1_1, We1_2, be1)
    float4* eaS = (float4*)(sm + 16896 + 512);     // 64
    float* envS = sm + 16896 + 512 + 256;          // 64
    float* be2S = envS + ET;                       // 128
    int* srcS = (int*)(be2S + CH);                 // 64
    int* dstS = srcS + ET;                         // 64

    int tid = threadIdx.x;
    // fill B: for kg,tig,n -> (We2[(kg*8+tig)][n], We2[(kg*8+tig+4)][n])
    for (int i = tid; i < 16 * 4 * 128; i += 128) {
        int kg = i >> 9, rem = i & 511;
        int tg = rem >> 7, n = rem & 127;
        int k1 = kg * 8 + tg;
        WS2[(kg * 4 + tg) * SBU2 + n] =
            make_uint2(f2tf(We2[k1 * CH + n]), f2tf(We2[(k1 + 4) * CH + n]));
    }
    W1p[tid] = make_float4(We1[tid], We1[CH + tid], We1[2 * CH + tid], be1[tid]);
    be2S[tid] = be2[tid];
    __syncthreads();

    int lane = tid & 31, w = tid >> 5;
    int gid = lane >> 2, tig = lane & 3;
    int r0 = w * 16 + gid, r1 = r0 + 8;
    bool even = (tig & 1) == 0;
    int cb = (tig >> 1) * 4;

    for (int tile = blockIdx.x; tile < NETILES; tile += gridDim.x) {
        int e0 = tile * ET;
        if (tid < ET) {
            const float* eap = edge_attr + (size_t)(e0 + tid) * 3;
            eaS[tid] = make_float4(eap[0], eap[1], eap[2], 0.f);
            envS[tid] = g_env[e0 + tid];
            srcS[tid] = src[e0 + tid];
            dstS[tid] = dst[e0 + tid];
        }
        __syncthreads();

        float4 eA = eaS[r0];
        float4 eB = eaS[r1];

        float acc[16][4];
#pragma unroll
        for (int i = 0; i < 16; i++)
#pragma unroll
            for (int q = 0; q < 4; q++) acc[i][q] = 0.f;

#pragma unroll 4
        for (int kg = 0; kg < 16; kg++) {
            int k1 = kg * 8 + tig;
            float4 wa = W1p[k1];
            float4 wb = W1p[k1 + 4];
            float uA1 = fmaf(eA.x, wa.x, fmaf(eA.y, wa.y, fmaf(eA.z, wa.z, wa.w)));
            float uB1 = fmaf(eB.x, wa.x, fmaf(eB.y, wa.y, fmaf(eB.z, wa.z, wa.w)));
            float uA2 = fmaf(eA.x, wb.x, fmaf(eA.y, wb.y, fmaf(eA.z, wb.z, wb.w)));
            float uB2 = fmaf(eB.x, wb.x, fmaf(eB.y, wb.y, fmaf(eB.z, wb.z, wb.w)));
            uint32_t a0 = f2tf(sspf(uA1));
            uint32_t a1 = f2tf(sspf(uB1));
            uint32_t a2 = f2tf(sspf(uA2));
            uint32_t a3 = f2tf(sspf(uB2));
            const uint2* bp = WS2 + (kg * 4 + tig) * SBU2 + gid;
#pragma unroll
            for (int ni = 0; ni < 16; ni++) {
                uint2 bb = bp[ni * 8];
                mma8(acc[ni], a0, a1, a2, a3, bb.x, bb.y);
            }
        }

        // epilogue: pair lanes -> v4, gather hin, modulate, RED scatter
        int rr = even ? r0 : r1;
        int s = srcS[rr], d = dstS[rr];
        float ev = envS[rr];
        const float* hrow = g_hin + (size_t)s * CH;
        float* arow = g_agg + (size_t)d * CH;
#pragma unroll
        for (int ni = 0; ni < 16; ni++) {
            float sA = even ? acc[ni][2] : acc[ni][0];
            float rA = __shfl_xor_sync(0xffffffffu, sA, 1);
            float sB = even ? acc[ni][3] : acc[ni][1];
            float rB = __shfl_xor_sync(0xffffffffu, sB, 1);
            float fx, fy, fz, fw;
            if (even) { fx = acc[ni][0]; fy = acc[ni][1]; fz = rA; fw = rB; }
            else      { fx = rA; fy = rB; fz = acc[ni][2]; fw = acc[ni][3]; }
            int c = cb + ni * 8;
            float4 h = *(const float4*)(hrow + c);
            float4 bb = *(const float4*)(be2S + c);
            red_add_v4(arow + c,
                       h.x * (fx + bb.x) * ev,
                       h.y * (fy + bb.y) * ev,
                       h.z * (fz + bb.z) * ev,
                       h.w * (fw + bb.w) * ev);
        }
        __syncthreads();
    }
}

// ---------------- readout MLP ----------------
__global__ void readout_kernel(const float* __restrict__ W_r1,
                               const float* __restrict__ b_r1,
                               const float* __restrict__ W_r2,
                               const float* __restrict__ b_r2,
                               float* __restrict__ out) {
    int g = blockIdx.x;
    int t = threadIdx.x;
    float acc = b_r1[t];
    for (int c = 0; c < CH; c++) acc += g_hg[g * CH + c] * W_r1[c * 32 + t];
    float r = sspf(acc);
    float p = r * W_r2[t];
#pragma unroll
    for (int o = 16; o; o >>= 1) p += __shfl_xor_sync(0xffffffffu, p, o);
    if (t == 0) out[g] = sspf(p + b_r2[0]);
}

// ---------------- launch ----------------
extern "C" void kernel_launch(void* const* d_in, const int* in_sizes, int n_in,
                              void* d_out, int out_size) {
    const float* x      = (const float*)d_in[0];
    const int*   eidx   = (const int*)d_in[1];
    const float* ew     = (const float*)d_in[2];
    const float* ea     = (const float*)d_in[3];
    const int*   batch  = (const int*)d_in[4];
    const float* W_l1   = (const float*)d_in[5];
    const float* b_l1   = (const float*)d_in[6];
    const float* W_l2   = (const float*)d_in[7];
    const float* b_l2   = (const float*)d_in[8];
    const float* bn_g   = (const float*)d_in[9];
    const float* bn_b   = (const float*)d_in[10];
    const float* Wi_in  = (const float*)d_in[11];
    const float* bi_in  = (const float*)d_in[12];
    const float* We1    = (const float*)d_in[13];
    const float* be1    = (const float*)d_in[14];
    const float* We2    = (const float*)d_in[15];
    const float* be2    = (const float*)d_in[16];
    const float* Wi_out = (const float*)d_in[17];
    const float* bi_out = (const float*)d_in[18];
    const float* W_r1   = (const float*)d_in[19];
    const float* b_r1   = (const float*)d_in[20];
    const float* W_r2   = (const float*)d_in[21];
    const float* b_r2   = (const float*)d_in[22];
    float* out = (float*)d_out;

    void *p_agg, *p_hg, *p_bns, *p_bnq;
    cudaGetSymbolAddress(&p_agg, g_agg);
    cudaGetSymbolAddress(&p_hg, g_hg);
    cudaGetSymbolAddress(&p_bns, g_bnsum);
    cudaGetSymbolAddress(&p_bnq, g_bnsq);

    cudaFuncSetAttribute(node_gemm<0,0>, cudaFuncAttributeMaxDynamicSharedMemorySize, NG_SMEM);
    cudaFuncSetAttribute(node_gemm<1,0>, cudaFuncAttributeMaxDynamicSharedMemorySize, NG_SMEM);
    cudaFuncSetAttribute(node_gemm<2,0>, cudaFuncAttributeMaxDynamicSharedMemorySize, NG_SMEM);
    cudaFuncSetAttribute(node_gemm<2,1>, cudaFuncAttributeMaxDynamicSharedMemorySize, NG_SMEM);
    cudaFuncSetAttribute(edge_kernel, cudaFuncAttributeMaxDynamicSharedMemorySize, EDGE_SMEM);

    cudaMemsetAsync(p_bns, 0, CH * sizeof(float));
    cudaMemsetAsync(p_bnq, 0, CH * sizeof(float));
    cudaMemsetAsync(p_hg, 0, NGR * CH * sizeof(float));

    const int ng_grid = 2 * 148;
    const int e_grid = 3 * 148;

    embed1_kernel<<<(NN * CH + 255) / 256, 256>>>(x, W_l1, b_l1);
    node_gemm<0,0><<<ng_grid, 256, NG_SMEM>>>(W_l2, b_l2, batch);

    bn_stats_kernel<<<256, 128>>>();
    bn_apply_kernel<<<(NN * CH + 255) / 256, 256>>>(bn_g, bn_b);

    env_kernel<<<(NE + 255) / 256, 256>>>(ew);

    for (int i = 0; i < NL; i++) {
        node_gemm<1,0><<<ng_grid, 256, NG_SMEM>>>(Wi_in + i * CH * CH, bi_in + i * CH, batch);
        cudaMemsetAsync(p_agg, 0, (size_t)NN * CH * sizeof(float));
        edge_kernel<<<e_grid, 128, EDGE_SMEM>>>(ea, eidx, eidx + NE,
                                                We1 + i * FE * CH, be1 + i * CH,
                                                We2 + i * CH * CH, be2 + i * CH);
        if (i < NL - 1)
            node_gemm<2,0><<<ng_grid, 256, NG_SMEM>>>(Wi_out + i * CH * CH, bi_out + i * CH, batch);
        else
            node_gemm<2,1><<<ng_grid, 256, NG_SMEM>>>(Wi_out + i * CH * CH, bi_out + i * CH, batch);
    }

    readout_kernel<<<NGR, 32>>>(W_r1, b_r1, W_r2, b_r2, out);
}

// round 6
// speedup vs baseline: 4.1944x; 1.0598x over previous
#include <cuda_runtime.h>
#include <cuda_fp16.h>
#include <math.h>
#include <stdint.h>

#define NN 50000
#define NE 800000
#define NGR 1024
#define CH 128
#define FIN 16
#define FE 3
#define NL 3
#define ET 64            // edges per tile
#define NETILES (NE / ET)
#define LN2F 0.69314718055994531f
#define L2EF 1.44269504088896341f
#define BN_EPS 1e-5f
#define SA 132   // A-operand smem row stride (floats), conflict-free
#define SB 136   // B-operand smem row stride (floats), conflict-free
#define SBU2 132 // edge B smem row stride in uint2: conflict-free

// ---------------- scratch ----------------
__device__ float g_h[NN * CH];
__device__ __half g_hin_h[NN * CH];
__device__ float g_agg[NN * CH];
__device__ float g_env[NE];
__device__ float g_bnsum[CH];
__device__ float g_bnsq[CH];
__device__ float g_hg[NGR * CH];
__device__ float g_Wc[FIN * CH];
__device__ float g_bc[CH];

__device__ __forceinline__ float ex2f(float x) {
    float r;
    asm("ex2.approx.f32 %0, %1;" : "=f"(r) : "f"(x));
    return r;
}
__device__ __forceinline__ float lg2f(float x) {
    float r;
    asm("lg2.approx.f32 %0, %1;" : "=f"(r) : "f"(x));
    return r;
}
__device__ __forceinline__ float sspf(float x) {
    float t = ex2f(-L2EF * fabsf(x));
    return fmaxf(x, 0.f) + LN2F * (lg2f(1.f + t) - 1.f);
}

__device__ __forceinline__ void red_add_v4(float* addr, float a, float b, float c, float d) {
    asm volatile("red.global.add.v4.f32 [%0], {%1,%2,%3,%4};"
                 :: "l"(addr), "f"(a), "f"(b), "f"(c), "f"(d) : "memory");
}

__device__ __forceinline__ uint32_t f2tf(float f) {
    uint32_t r;
    asm("cvt.rna.tf32.f32 %0, %1;" : "=r"(r) : "f"(f));
    return r;
}

__device__ __forceinline__ void mma8(float c[4], uint32_t a0, uint32_t a1, uint32_t a2, uint32_t a3,
                                     uint32_t b0, uint32_t b1) {
    asm volatile("mma.sync.aligned.m16n8k8.row.col.f32.tf32.tf32.f32 "
                 "{%0,%1,%2,%3},{%4,%5,%6,%7},{%8,%9},{%0,%1,%2,%3};"
                 : "+f"(c[0]), "+f"(c[1]), "+f"(c[2]), "+f"(c[3])
                 : "r"(a0), "r"(a1), "r"(a2), "r"(a3), "r"(b0), "r"(b1));
}

// ---------------- embed weight fold: Wc = W_l1@W_l2, bc = b_l1@W_l2 + b_l2 ----------------
__global__ void prep_embed(const float* __restrict__ W_l1, const float* __restrict__ b_l1,
                           const float* __restrict__ W_l2, const float* __restrict__ b_l2) {
    int i = blockIdx.x * blockDim.x + threadIdx.x;
    if (i < FIN * CH) {
        int f = i >> 7, j = i & 127;
        float acc = 0.f;
        for (int k = 0; k < CH; k++) acc += W_l1[f * CH + k] * W_l2[k * CH + j];
        g_Wc[i] = acc;
    } else if (i < FIN * CH + CH) {
        int j = i - FIN * CH;
        float acc = b_l2[j];
        for (int k = 0; k < CH; k++) acc += b_l1[k] * W_l2[k * CH + j];
        g_bc[j] = acc;
    }
}

// ---------------- embed: g_h = x @ Wc + bc ----------------
__global__ void embed_kernel(const float* __restrict__ x) {
    int idx = blockIdx.x * blockDim.x + threadIdx.x;
    if (idx >= NN * CH) return;
    int n = idx >> 7, j = idx & 127;
    const float* xr = x + n * FIN;
    float acc = g_bc[j];
#pragma unroll
    for (int f = 0; f < FIN; f++) acc += xr[f] * g_Wc[f * CH + j];
    g_h[idx] = acc;
}

// ---------------- persistent node GEMM ----------------
// MODE 1: g_hin_h = half(g_h @ W + b); also zero g_agg
// MODE 2: g_h    += ssp(g_agg @ W + b)   (+POOL: red to g_hg[batch])
#define NG_SMEM ((CH * SB + 64 * SA) * 4)

template <int MODE, int POOL>
__global__ __launch_bounds__(256, 2) void node_gemm(const float* __restrict__ W,
                                                    const float* __restrict__ b,
                                                    const int* __restrict__ batch) {
    extern __shared__ float sm[];
    uint32_t* WS = (uint32_t*)sm;          // [k][n], stride SB
    float* XSf = sm + CH * SB;             // 64 x SA
    uint32_t* XS = (uint32_t*)XSf;
    const float* X = (MODE == 1) ? g_h : g_agg;

    int tid = threadIdx.x;
    for (int i = tid; i < CH * CH; i += 256)
        WS[(i >> 7) * SB + (i & 127)] = f2tf(W[i]);

    int lane = tid & 31, w = tid >> 5;
    int gid = lane >> 2, tig = lane & 3;
    int wm = w & 3, wn = w >> 2;
    int r0 = wm * 16 + gid;
    const int NT = (NN + 63) / 64;

    for (int tile = blockIdx.x; tile < NT; tile += gridDim.x) {
        int nb = tile * 64;
        __syncthreads();
        for (int i = tid; i < 64 * CH; i += 256) {
            int r = i >> 7, c = i & 127;
            int n = nb + r;
            XS[r * SA + c] = (n < NN) ? f2tf(X[(size_t)n * CH + c]) : 0u;
        }
        __syncthreads();

        float acc[8][4];
#pragma unroll
        for (int i = 0; i < 8; i++)
#pragma unroll
            for (int q = 0; q < 4; q++) acc[i][q] = 0.f;

#pragma unroll 4
        for (int k0 = 0; k0 < CH; k0 += 8) {
            int k1 = k0 + tig, k2 = k1 + 4;
            uint32_t a0 = XS[r0 * SA + k1];
            uint32_t a1 = XS[(r0 + 8) * SA + k1];
            uint32_t a2 = XS[r0 * SA + k2];
            uint32_t a3 = XS[(r0 + 8) * SA + k2];
#pragma unroll
            for (int ni = 0; ni < 8; ni++) {
                uint32_t b0 = WS[k1 * SB + wn * 64 + ni * 8 + gid];
                uint32_t b1 = WS[k2 * SB + wn * 64 + ni * 8 + gid];
                mma8(acc[ni], a0, a1, a2, a3, b0, b1);
            }
        }
        __syncthreads();
#pragma unroll
        for (int ni = 0; ni < 8; ni++) {
            int c = wn * 64 + ni * 8 + 2 * tig;
            *(float2*)(XSf + r0 * SA + c) = make_float2(acc[ni][0], acc[ni][1]);
            *(float2*)(XSf + (r0 + 8) * SA + c) = make_float2(acc[ni][2], acc[ni][3]);
        }
        __syncthreads();
#pragma unroll
        for (int it = 0; it < 8; it++) {
            int chunk = tid + it * 256;
            int r = chunk >> 5, cq = (chunk & 31) * 4;
            int n = nb + r;
            if (n >= NN) continue;
            float4 v = *(float4*)(XSf + r * SA + cq);
            float4 bb = *(const float4*)(b + cq);
            if (MODE == 2) {
                float* base = g_h + (size_t)n * CH + cq;
                float4 old = *(float4*)base;
                old.x += sspf(v.x + bb.x);
                old.y += sspf(v.y + bb.y);
                old.z += sspf(v.z + bb.z);
                old.w += sspf(v.w + bb.w);
                *(float4*)base = old;
                if (POOL) {
                    int g = batch[n];
                    red_add_v4(g_hg + (size_t)g * CH + cq, old.x, old.y, old.z, old.w);
                }
            } else {
                v.x += bb.x; v.y += bb.y; v.z += bb.z; v.w += bb.w;
                union { __half2 h[2]; uint2 u; } pk;
                pk.h[0] = __floats2half2_rn(v.x, v.y);
                pk.h[1] = __floats2half2_rn(v.z, v.w);
                *(uint2*)(g_hin_h + (size_t)n * CH + cq) = pk.u;
                *(float4*)(g_agg + (size_t)n * CH + cq) = make_float4(0.f, 0.f, 0.f, 0.f);
            }
        }
    }
}

// ---------------- BatchNorm ----------------
__global__ void bn_stats_kernel() {
    int c = threadIdx.x;
    float s = 0.f, q = 0.f;
    for (int n = blockIdx.x; n < NN; n += gridDim.x) {
        float v = g_h[n * CH + c];
        s += v; q += v * v;
    }
    atomicAdd(&g_bnsum[c], s);
    atomicAdd(&g_bnsq[c], q);
}

__global__ void bn_apply_kernel(const float* __restrict__ bn_g,
                                const float* __restrict__ bn_b) {
    int idx = blockIdx.x * blockDim.x + threadIdx.x;
    if (idx >= NN * CH) return;
    int c = idx & 127;
    float mu = g_bnsum[c] * (1.f / NN);
    float var = g_bnsq[c] * (1.f / NN) - mu * mu;
    g_h[idx] = (g_h[idx] - mu) * rsqrtf(var + BN_EPS) * bn_g[c] + bn_b[c];
}

// ---------------- envelope ----------------
__global__ void env_kernel(const float* __restrict__ ew) {
    int idx = blockIdx.x * blockDim.x + threadIdx.x;
    if (idx >= NE) return;
    g_env[idx] = 0.5f * (cosf(ew[idx] * 0.31415926535897931f) + 1.f);
}

// ---------------- persistent fused edge kernel ----------------
#define EDGE_SMEM ((16896 + 512 + 256 + 64 + 128 + 64 + 64) * 4)

__global__ __launch_bounds__(128, 3) void edge_kernel(
    const float* __restrict__ edge_attr,
    const int* __restrict__ src, const int* __restrict__ dst,
    const float* __restrict__ We1, const float* __restrict__ be1,
    const float* __restrict__ We2, const float* __restrict__ be2) {
    extern __shared__ float sm[];
    uint2* WS2 = (uint2*)sm;                       // [(kg*4+tig)*SBU2 + n] = (tf32 W[k1][n], tf32 W[k1+4][n])
    float4* W1p = (float4*)(sm + 16896);           // 128: (We1_0, We1_1, We1_2, be1)
    float4* eaS = (float4*)(sm + 16896 + 512);     // 64
    float* envS = sm + 16896 + 512 + 256;          // 64
    float* be2S = envS + ET;                       // 128
    int* srcS = (int*)(be2S + CH);                 // 64
    int* dstS = srcS + ET;                         // 64

    int tid = threadIdx.x;
    for (int i = tid; i < 16 * 4 * 128; i += 128) {
        int kg = i >> 9, rem = i & 511;
        int tg = rem >> 7, n = rem & 127;
        int k1 = kg * 8 + tg;
        WS2[(kg * 4 + tg) * SBU2 + n] =
            make_uint2(f2tf(We2[k1 * CH + n]), f2tf(We2[(k1 + 4) * CH + n]));
    }
    W1p[tid] = make_float4(We1[tid], We1[CH + tid], We1[2 * CH + tid], be1[tid]);
    be2S[tid] = be2[tid];
    __syncthreads();

    int lane = tid & 31, w = tid >> 5;
    int gid = lane >> 2, tig = lane & 3;
    int r0 = w * 16 + gid, r1 = r0 + 8;
    bool even = (tig & 1) == 0;
    int cb = (tig >> 1) * 4;

    for (int tile = blockIdx.x; tile < NETILES; tile += gridDim.x) {
        int e0 = tile * ET;
        if (tid < ET) {
            const float* eap = edge_attr + (size_t)(e0 + tid) * 3;
            eaS[tid] = make_float4(eap[0], eap[1], eap[2], 0.f);
            envS[tid] = g_env[e0 + tid];
            srcS[tid] = src[e0 + tid];
            dstS[tid] = dst[e0 + tid];
        }
        __syncthreads();

        float4 eA = eaS[r0];
        float4 eB = eaS[r1];

        float acc[16][4];
#pragma unroll
        for (int i = 0; i < 16; i++)
#pragma unroll
            for (int q = 0; q < 4; q++) acc[i][q] = 0.f;

#pragma unroll 4
        for (int kg = 0; kg < 16; kg++) {
            int k1 = kg * 8 + tig;
            float4 wa = W1p[k1];
            float4 wb = W1p[k1 + 4];
            float uA1 = fmaf(eA.x, wa.x, fmaf(eA.y, wa.y, fmaf(eA.z, wa.z, wa.w)));
            float uB1 = fmaf(eB.x, wa.x, fmaf(eB.y, wa.y, fmaf(eB.z, wa.z, wa.w)));
            float uA2 = fmaf(eA.x, wb.x, fmaf(eA.y, wb.y, fmaf(eA.z, wb.z, wb.w)));
            float uB2 = fmaf(eB.x, wb.x, fmaf(eB.y, wb.y, fmaf(eB.z, wb.z, wb.w)));
            uint32_t a0 = f2tf(sspf(uA1));
            uint32_t a1 = f2tf(sspf(uB1));
            uint32_t a2 = f2tf(sspf(uA2));
            uint32_t a3 = f2tf(sspf(uB2));
            const uint2* bp = WS2 + (kg * 4 + tig) * SBU2 + gid;
#pragma unroll
            for (int ni = 0; ni < 16; ni++) {
                uint2 bb = bp[ni * 8];
                mma8(acc[ni], a0, a1, a2, a3, bb.x, bb.y);
            }
        }

        // epilogue: pair lanes -> v4, gather fp16 hin, modulate, RED scatter fp32
        int rr = even ? r0 : r1;
        int s = srcS[rr], d = dstS[rr];
        float ev = envS[rr];
        const __half* hrow = g_hin_h + (size_t)s * CH;
        float* arow = g_agg + (size_t)d * CH;
#pragma unroll
        for (int ni = 0; ni < 16; ni++) {
            float sA = even ? acc[ni][2] : acc[ni][0];
            float rA = __shfl_xor_sync(0xffffffffu, sA, 1);
            float sB = even ? acc[ni][3] : acc[ni][1];
            float rB = __shfl_xor_sync(0xffffffffu, sB, 1);
            float fx, fy, fz, fw;
            if (even) { fx = acc[ni][0]; fy = acc[ni][1]; fz = rA; fw = rB; }
            else      { fx = rA; fy = rB; fz = acc[ni][2]; fw = acc[ni][3]; }
            int c = cb + ni * 8;
            uint2 hp = *(const uint2*)(hrow + c);
            float2 h01 = __half22float2(*(__half2*)&hp.x);
            float2 h23 = __half22float2(*(__half2*)&hp.y);
            float4 bb = *(const float4*)(be2S + c);
            red_add_v4(arow + c,
                       h01.x * (fx + bb.x) * ev,
                       h01.y * (fy + bb.y) * ev,
                       h23.x * (fz + bb.z) * ev,
                       h23.y * (fw + bb.w) * ev);
        }
        __syncthreads();
    }
}

// ---------------- readout MLP ----------------
__global__ void readout_kernel(const float* __restrict__ W_r1,
                               const float* __restrict__ b_r1,
                               const float* __restrict__ W_r2,
                               const float* __restrict__ b_r2,
                               float* __restrict__ out) {
    int g = blockIdx.x;
    int t = threadIdx.x;
    float acc = b_r1[t];
    for (int c = 0; c < CH; c++) acc += g_hg[g * CH + c] * W_r1[c * 32 + t];
    float r = sspf(acc);
    float p = r * W_r2[t];
#pragma unroll
    for (int o = 16; o; o >>= 1) p += __shfl_xor_sync(0xffffffffu, p, o);
    if (t == 0) out[g] = sspf(p + b_r2[0]);
}

// ---------------- launch ----------------
extern "C" void kernel_launch(void* const* d_in, const int* in_sizes, int n_in,
                              void* d_out, int out_size) {
    const float* x      = (const float*)d_in[0];
    const int*   eidx   = (const int*)d_in[1];
    const float* ew     = (const float*)d_in[2];
    const float* ea     = (const float*)d_in[3];
    const int*   batch  = (const int*)d_in[4];
    const float* W_l1   = (const float*)d_in[5];
    const float* b_l1   = (const float*)d_in[6];
    const float* W_l2   = (const float*)d_in[7];
    const float* b_l2   = (const float*)d_in[8];
    const float* bn_g   = (const float*)d_in[9];
    const float* bn_b   = (const float*)d_in[10];
    const float* Wi_in  = (const float*)d_in[11];
    const float* bi_in  = (const float*)d_in[12];
    const float* We1    = (const float*)d_in[13];
    const float* be1    = (const float*)d_in[14];
    const float* We2    = (const float*)d_in[15];
    const float* be2    = (const float*)d_in[16];
    const float* Wi_out = (const float*)d_in[17];
    const float* bi_out = (const float*)d_in[18];
    const float* W_r1   = (const float*)d_in[19];
    const float* b_r1   = (const float*)d_in[20];
    const float* W_r2   = (const float*)d_in[21];
    const float* b_r2   = (const float*)d_in[22];
    float* out = (float*)d_out;

    void *p_hg, *p_bns, *p_bnq;
    cudaGetSymbolAddress(&p_hg, g_hg);
    cudaGetSymbolAddress(&p_bns, g_bnsum);
    cudaGetSymbolAddress(&p_bnq, g_bnsq);

    cudaFuncSetAttribute(node_gemm<1,0>, cudaFuncAttributeMaxDynamicSharedMemorySize, NG_SMEM);
    cudaFuncSetAttribute(node_gemm<2,0>, cudaFuncAttributeMaxDynamicSharedMemorySize, NG_SMEM);
    cudaFuncSetAttribute(node_gemm<2,1>, cudaFuncAttributeMaxDynamicSharedMemorySize, NG_SMEM);
    cudaFuncSetAttribute(edge_kernel, cudaFuncAttributeMaxDynamicSharedMemorySize, EDGE_SMEM);

    cudaMemsetAsync(p_bns, 0, CH * sizeof(float));
    cudaMemsetAsync(p_bnq, 0, CH * sizeof(float));
    cudaMemsetAsync(p_hg, 0, NGR * CH * sizeof(float));

    const int ng_grid = 2 * 148;
    const int e_grid = 3 * 148;

    prep_embed<<<(FIN * CH + CH + 255) / 256, 256>>>(W_l1, b_l1, W_l2, b_l2);
    embed_kernel<<<(NN * CH + 255) / 256, 256>>>(x);

    bn_stats_kernel<<<256, 128>>>();
    bn_apply_kernel<<<(NN * CH + 255) / 256, 256>>>(bn_g, bn_b);

    env_kernel<<<(NE + 255) / 256, 256>>>(ew);

    for (int i = 0; i < NL; i++) {
        node_gemm<1,0><<<ng_grid, 256, NG_SMEM>>>(Wi_in + i * CH * CH, bi_in + i * CH, batch);
        edge_kernel<<<e_grid, 128, EDGE_SMEM>>>(ea, eidx, eidx + NE,
                                                We1 + i * FE * CH, be1 + i * CH,
                                                We2 + i * CH * CH, be2 + i * CH);
        if (i < NL - 1)
            node_gemm<2,0><<<ng_grid, 256, NG_SMEM>>>(Wi_out + i * CH * CH, bi_out + i * CH, batch);
        else
            node_gemm<2,1><<<ng_grid, 256, NG_SMEM>>>(Wi_out + i * CH * CH, bi_out + i * CH, batch);
    }

    readout_kernel<<<NGR, 32>>>(W_r1, b_r1, W_r2, b_r2, out);
}